// round 9
// baseline (speedup 1.0000x reference)
#include <cuda_runtime.h>

// Problem constants
#define Bq     8
#define Cq     128
#define HEADS  8
#define HC     16            // channels per head
#define Nq     16384         // H*W
#define NBH    (Bq*HEADS)    // 64

// Kernel-1 tiling: 128-thread CTAs, 16 chunks, 64-wide tiles
#define CHUNKS      16
#define CHUNK_COLS  (Nq/CHUNKS)        // 1024
#define TILE        64
#define NTILES      (CHUNK_COLS/TILE)  // 16
#define PAD         72                 // row stride (288B = 18*16 -> 16B-aligned)
#define THREADS1    128

// Kernel-2 tiling: 2 columns per thread, 256 threads -> 512 columns per block
#define COLS2       512

// Scratch (no allocations allowed -> __device__ globals)
__device__ float g_pctx[NBH][CHUNKS][HC][HC];   // unnormalized partial context
__device__ float g_psum[NBH][CHUNKS][HC];       // partial row sums of exp(k)
__device__ float g_ctx [NBH][HC][HC];           // normalized context

// ---- packed f32x2 helpers (ptxas never auto-fuses) ----
__device__ __forceinline__ unsigned long long fma2(unsigned long long a,
                                                   unsigned long long b,
                                                   unsigned long long c) {
    unsigned long long d;
    asm("fma.rn.f32x2 %0, %1, %2, %3;" : "=l"(d) : "l"(a), "l"(b), "l"(c));
    return d;
}
__device__ __forceinline__ unsigned long long pack2(float lo, float hi) {
    unsigned long long d;
    asm("mov.b64 %0, {%1, %2};" : "=l"(d) : "f"(lo), "f"(hi));
    return d;
}
__device__ __forceinline__ void unpack2(unsigned long long v, float& lo, float& hi) {
    asm("mov.b64 {%0, %1}, %2;" : "=f"(lo), "=f"(hi) : "l"(v));
}

// ---------------------------------------------------------------------------
// Kernel 1: per (b,h,chunk) partial  ctx'[r][c] = sum_n exp(k[r,n]) * v[c,n]
// 128 threads, 6 CTAs/SM (reg cap ~85: no spill risk, 6 independent barrier
// groups per SM). Double-buffered pipeline, one barrier per tile.
// ---------------------------------------------------------------------------
__global__ __launch_bounds__(THREADS1, 6)
void ctx_partial_kernel(const float* __restrict__ x1, const float* __restrict__ x2) {
    __shared__ float e_sm[2][HC][PAD];
    __shared__ float v_sm[2][HC][PAD];
    __shared__ float red_sm[4][256];    // per-warp 16x16 partial tiles
    __shared__ float rs_sm[THREADS1];   // per-thread row sums

    const int tid   = threadIdx.x;
    const int chunk = blockIdx.x;
    const int h     = blockIdx.y;
    const int b     = blockIdx.z;
    const int bh    = b * HEADS + h;

    const int base  = (b * Cq + h * HC) * Nq + chunk * CHUNK_COLS;
    const float* kptr = x2 + base;   // keys/queries come from x2
    const float* vptr = x1 + base;   // values come from x1

    // producer mapping: 8 threads per row, 2 float4 each
    const int pr  = tid >> 3;        // row 0..15
    const int pl  = tid & 7;
    const int t4a = pl;              // float4 index 0..7
    const int t4b = pl + 8;          // float4 index 8..15

    // consumer mapping: 4 warps, warp w owns tile cols [w*16, w*16+16)
    const int w  = tid >> 5;
    const int l  = tid & 31;
    const int rg = l >> 3;           // ctx rows rg*4 .. rg*4+3
    const int cg = l & 7;            // ctx cols cg*2, cg*2+1

    unsigned long long accp[4][2];
    #pragma unroll
    for (int a = 0; a < 4; a++) { accp[a][0] = 0ull; accp[a][1] = 0ull; }
    float rowsum = 0.f;

    float4 kv0, kv1, vv0, vv1;

    // ---- prologue: load + stage tile 0 into buffer 0 ----
    {
        const int off = pr * Nq;
        kv0 = *(const float4*)(kptr + off + 4 * t4a);
        kv1 = *(const float4*)(kptr + off + 4 * t4b);
        vv0 = *(const float4*)(vptr + off + 4 * t4a);
        vv1 = *(const float4*)(vptr + off + 4 * t4b);
        float4 e0, e1;
        e0.x = __expf(kv0.x); e0.y = __expf(kv0.y); e0.z = __expf(kv0.z); e0.w = __expf(kv0.w);
        e1.x = __expf(kv1.x); e1.y = __expf(kv1.y); e1.z = __expf(kv1.z); e1.w = __expf(kv1.w);
        rowsum += e0.x + e0.y + e0.z + e0.w + e1.x + e1.y + e1.z + e1.w;
        *(float4*)&e_sm[0][pr][4 * t4a] = e0;
        *(float4*)&e_sm[0][pr][4 * t4b] = e1;
        *(float4*)&v_sm[0][pr][4 * t4a] = vv0;
        *(float4*)&v_sm[0][pr][4 * t4b] = vv1;
    }
    __syncthreads();

    for (int tile = 0; tile < NTILES; tile++) {
        const int cur = tile & 1;
        const int nxt = cur ^ 1;

        // ---- issue loads for tile+1 ----
        if (tile + 1 < NTILES) {
            const int off = pr * Nq + (tile + 1) * TILE;
            kv0 = *(const float4*)(kptr + off + 4 * t4a);
            kv1 = *(const float4*)(kptr + off + 4 * t4b);
            vv0 = *(const float4*)(vptr + off + 4 * t4a);
            vv1 = *(const float4*)(vptr + off + 4 * t4b);
        }

        // ---- consume tile from buffer `cur` (f32x2 FMAs) ----
        #pragma unroll
        for (int tb = 0; tb < 16; tb += 4) {
            const int t = w * 16 + tb;   // 16B-aligned (t % 4 == 0)
            ulonglong2 er2[4], vc2[2];
            #pragma unroll
            for (int jr = 0; jr < 4; jr++)
                er2[jr] = *(const ulonglong2*)&e_sm[cur][rg * 4 + jr][t];
            #pragma unroll
            for (int jc = 0; jc < 2; jc++)
                vc2[jc] = *(const ulonglong2*)&v_sm[cur][cg * 2 + jc][t];
            #pragma unroll
            for (int jr = 0; jr < 4; jr++) {
                #pragma unroll
                for (int jc = 0; jc < 2; jc++) {
                    accp[jr][jc] = fma2(er2[jr].x, vc2[jc].x, accp[jr][jc]);
                    accp[jr][jc] = fma2(er2[jr].y, vc2[jc].y, accp[jr][jc]);
                }
            }
        }

        // ---- stage tile+1 into buffer `nxt` ----
        if (tile + 1 < NTILES) {
            float4 e0, e1;
            e0.x = __expf(kv0.x); e0.y = __expf(kv0.y); e0.z = __expf(kv0.z); e0.w = __expf(kv0.w);
            e1.x = __expf(kv1.x); e1.y = __expf(kv1.y); e1.z = __expf(kv1.z); e1.w = __expf(kv1.w);
            rowsum += e0.x + e0.y + e0.z + e0.w + e1.x + e1.y + e1.z + e1.w;
            *(float4*)&e_sm[nxt][pr][4 * t4a] = e0;
            *(float4*)&e_sm[nxt][pr][4 * t4b] = e1;
            *(float4*)&v_sm[nxt][pr][4 * t4a] = vv0;
            *(float4*)&v_sm[nxt][pr][4 * t4b] = vv1;
        }
        __syncthreads();
    }

    // ---- epilogue: horizontal add, cross-warp reduce, write partials ----
    #pragma unroll
    for (int jr = 0; jr < 4; jr++)
        #pragma unroll
        for (int jc = 0; jc < 2; jc++) {
            float lo, hi;
            unpack2(accp[jr][jc], lo, hi);
            red_sm[w][(rg * 4 + jr) * 16 + (cg * 2 + jc)] = lo + hi;
        }
    rs_sm[tid] = rowsum;
    __syncthreads();

    #pragma unroll
    for (int rep = 0; rep < 2; rep++) {
        const int idx = tid + rep * THREADS1;
        float p = red_sm[0][idx] + red_sm[1][idx] + red_sm[2][idx] + red_sm[3][idx];
        g_pctx[bh][chunk][idx >> 4][idx & 15] = p;
    }

    if (tid < HC) {
        float s = 0.f;
        #pragma unroll
        for (int j = 0; j < 8; j++) s += rs_sm[tid * 8 + j];
        g_psum[bh][chunk][tid] = s;
    }
}

// ---------------------------------------------------------------------------
// Kernel 1.5: reduce chunk partials, normalize by row sums -> g_ctx
// ---------------------------------------------------------------------------
__global__ __launch_bounds__(256)
void ctx_reduce_kernel() {
    __shared__ float sinv[HC];
    const int bh  = blockIdx.x;
    const int tid = threadIdx.x;

    if (tid < HC) {
        float s = 0.f;
        #pragma unroll
        for (int c = 0; c < CHUNKS; c++) s += g_psum[bh][c][tid];
        sinv[tid] = 1.0f / s;
    }
    __syncthreads();

    const int r = tid >> 4, cc = tid & 15;
    float a = 0.f;
    #pragma unroll
    for (int c = 0; c < CHUNKS; c++) a += g_pctx[bh][c][r][cc];
    g_ctx[bh][r][cc] = a * sinv[r];
}

// ---------------------------------------------------------------------------
// Kernel 2: out[v][n] = (sum_k ctx[k][v] * exp(k[k,n])) / (sum_k exp(k[k,n]))
// 2 columns per thread; accumulators packed over the v-dimension so ctx pairs
// load straight from smem (no dup) and only the exp is duplicated (1 mov).
// ~50 regs -> 4 CTAs/SM.
// ---------------------------------------------------------------------------
__global__ __launch_bounds__(256, 4)
void attend_kernel(const float* __restrict__ x2, float* __restrict__ out) {
    __shared__ float ctx_sm[HC][HC];   // ctx[k][v], rows 64B (16B-aligned)

    const int tid = threadIdx.x;
    const int h   = blockIdx.y;
    const int b   = blockIdx.z;
    const int bh  = b * HEADS + h;

    ((float*)ctx_sm)[tid] = ((const float*)g_ctx[bh])[tid];

    const int nn = blockIdx.x * COLS2 + 2 * tid;
    const float* kbase = x2  + (b * Cq + h * HC) * Nq + nn;
    float*       obase = out + (b * Cq + h * HC) * Nq + nn;
    __syncthreads();

    // accA: column n, accB: column n+1; each holds 8 packed {v, v+1} pairs
    unsigned long long accA[8], accB[8];
    #pragma unroll
    for (int j = 0; j < 8; j++) { accA[j] = 0ull; accB[j] = 0ull; }
    float sx = 0.f, sy = 0.f;

    #pragma unroll
    for (int k = 0; k < HC; k++) {
        float2 kv = *(const float2*)(kbase + k * Nq);
        const float ex = __expf(kv.x), ey = __expf(kv.y);
        sx += ex; sy += ey;
        const unsigned long long eA = pack2(ex, ex);
        const unsigned long long eB = pack2(ey, ey);
        #pragma unroll
        for (int v = 0; v < HC; v += 4) {
            // {ctx[k][v],ctx[k][v+1]},{ctx[k][v+2],ctx[k][v+3]} in one LDS.128
            ulonglong2 c2 = *(const ulonglong2*)&ctx_sm[k][v];
            accA[v / 2]     = fma2(eA, c2.x, accA[v / 2]);
            accB[v / 2]     = fma2(eB, c2.x, accB[v / 2]);
            accA[v / 2 + 1] = fma2(eA, c2.y, accA[v / 2 + 1]);
            accB[v / 2 + 1] = fma2(eB, c2.y, accB[v / 2 + 1]);
        }
    }

    const float rx = 1.0f / sx, ry = 1.0f / sy;
    #pragma unroll
    for (int j = 0; j < 8; j++) {
        float a0, a1, b0, b1;
        unpack2(accA[j], a0, a1);   // rows 2j, 2j+1 for column n
        unpack2(accB[j], b0, b1);   // rows 2j, 2j+1 for column n+1
        float2 o0, o1;
        o0.x = a0 * rx; o0.y = b0 * ry;
        o1.x = a1 * rx; o1.y = b1 * ry;
        *(float2*)(obase + (2 * j)     * Nq) = o0;
        *(float2*)(obase + (2 * j + 1) * Nq) = o1;
    }
}

// ---------------------------------------------------------------------------
extern "C" void kernel_launch(void* const* d_in, const int* in_sizes, int n_in,
                              void* d_out, int out_size) {
    const float* x1 = (const float*)d_in[0];   // values
    const float* x2 = (const float*)d_in[1];   // keys / queries
    float* out = (float*)d_out;

    ctx_partial_kernel<<<dim3(CHUNKS, HEADS, Bq), THREADS1>>>(x1, x2);
    ctx_reduce_kernel<<<NBH, 256>>>();
    attend_kernel<<<dim3(Nq / COLS2, HEADS, Bq), 256>>>(x2, out);
}

// round 11
// speedup vs baseline: 1.2502x; 1.2502x over previous
#include <cuda_runtime.h>

// Problem constants
#define Bq     8
#define Cq     128
#define HEADS  8
#define HC     16            // channels per head
#define Nq     16384         // H*W
#define NBH    (Bq*HEADS)    // 64

// Kernel-1 tiling (R4 structure, finer chunking for occupancy)
#define CHUNKS      16
#define CHUNK_COLS  (Nq/CHUNKS)        // 1024
#define TILE        128
#define NTILES      (CHUNK_COLS/TILE)  // 8
#define PAD         132                // row stride (528B = 33*16 -> 16B-aligned)

// Kernel-2 tiling: 4 columns per thread, 256 threads -> 1024 columns per block
#define COLS2       1024

// Scratch (no allocations allowed -> __device__ globals)
__device__ float g_pctx[NBH][CHUNKS][HC][HC];   // unnormalized partial context
__device__ float g_psum[NBH][CHUNKS][HC];       // partial row sums of exp(k)
__device__ float g_ctx [NBH][HC][HC];           // normalized context

// ---- packed f32x2 helpers (ptxas never auto-fuses) ----
__device__ __forceinline__ unsigned long long fma2(unsigned long long a,
                                                   unsigned long long b,
                                                   unsigned long long c) {
    unsigned long long d;
    asm("fma.rn.f32x2 %0, %1, %2, %3;" : "=l"(d) : "l"(a), "l"(b), "l"(c));
    return d;
}
__device__ __forceinline__ unsigned long long add2(unsigned long long a,
                                                   unsigned long long b) {
    unsigned long long d;
    asm("add.rn.f32x2 %0, %1, %2;" : "=l"(d) : "l"(a), "l"(b));
    return d;
}
__device__ __forceinline__ unsigned long long pack2(float lo, float hi) {
    unsigned long long d;
    asm("mov.b64 %0, {%1, %2};" : "=l"(d) : "f"(lo), "f"(hi));
    return d;
}
__device__ __forceinline__ void unpack2(unsigned long long v, float& lo, float& hi) {
    asm("mov.b64 {%0, %1}, %2;" : "=f"(lo), "=f"(hi) : "l"(v));
}

// ---------------------------------------------------------------------------
// Kernel 1: per (b,h,chunk) partial  ctx'[r][c] = sum_n exp(k[r,n]) * v[c,n]
// R4 structure: 256 threads, double-buffered smem pipeline, one barrier per
// tile, f32x2-packed accumulation. Grid doubled (CHUNKS=16) so the SM can
// actually hold its reg-limit of 4 CTAs.
// ---------------------------------------------------------------------------
__global__ __launch_bounds__(256)
void ctx_partial_kernel(const float* __restrict__ x1, const float* __restrict__ x2) {
    __shared__ float e_sm[2][HC][PAD];
    __shared__ float v_sm[2][HC][PAD];
    __shared__ float red_sm[8 * 256];   // per-warp ctx partials
    __shared__ float rs_sm[256];        // per-thread row sums

    const int tid   = threadIdx.x;
    const int chunk = blockIdx.x;
    const int h     = blockIdx.y;
    const int b     = blockIdx.z;
    const int bh    = b * HEADS + h;

    const int base  = (b * Cq + h * HC) * Nq + chunk * CHUNK_COLS;
    const float* kptr = x2 + base;   // keys/queries come from x2
    const float* vptr = x1 + base;   // values come from x1

    const int pr = tid >> 4;   // producer row (0..15)
    const int pl = tid & 15;   // producer lane within row
    const int w  = tid >> 5;   // warp id (0..7)
    const int l  = tid & 31;
    const int rg = l >> 3;     // row group: rows rg*4 .. rg*4+3
    const int cg = l & 7;      // col group: cols cg*2, cg*2+1

    unsigned long long accp[4][2];   // packed partial-pair accumulators
    #pragma unroll
    for (int a = 0; a < 4; a++) { accp[a][0] = 0ull; accp[a][1] = 0ull; }
    float rowsum = 0.f;

    const int t4a = pl;            // float4 index 0..15
    const int t4b = pl + 16;       // float4 index 16..31

    float4 kv0, kv1, vv0, vv1;     // staging registers for the in-flight tile

    // ---- prologue: load + stage tile 0 into buffer 0 ----
    {
        const int off = pr * Nq;
        kv0 = *(const float4*)(kptr + off + 4 * t4a);
        kv1 = *(const float4*)(kptr + off + 4 * t4b);
        vv0 = *(const float4*)(vptr + off + 4 * t4a);
        vv1 = *(const float4*)(vptr + off + 4 * t4b);
        float4 e0, e1;
        e0.x = __expf(kv0.x); e0.y = __expf(kv0.y); e0.z = __expf(kv0.z); e0.w = __expf(kv0.w);
        e1.x = __expf(kv1.x); e1.y = __expf(kv1.y); e1.z = __expf(kv1.z); e1.w = __expf(kv1.w);
        rowsum += e0.x + e0.y + e0.z + e0.w + e1.x + e1.y + e1.z + e1.w;
        *(float4*)&e_sm[0][pr][4 * t4a] = e0;
        *(float4*)&e_sm[0][pr][4 * t4b] = e1;
        *(float4*)&v_sm[0][pr][4 * t4a] = vv0;
        *(float4*)&v_sm[0][pr][4 * t4b] = vv1;
    }
    __syncthreads();

    for (int tile = 0; tile < NTILES; tile++) {
        const int cur = tile & 1;
        const int nxt = cur ^ 1;

        // ---- issue loads for tile+1 (latency hidden by consume below) ----
        if (tile + 1 < NTILES) {
            const int off = pr * Nq + (tile + 1) * TILE;
            kv0 = *(const float4*)(kptr + off + 4 * t4a);
            kv1 = *(const float4*)(kptr + off + 4 * t4b);
            vv0 = *(const float4*)(vptr + off + 4 * t4a);
            vv1 = *(const float4*)(vptr + off + 4 * t4b);
        }

        // ---- consume tile from smem buffer `cur` (f32x2-packed FMAs) ----
        #pragma unroll
        for (int tb = 0; tb < 16; tb += 4) {
            const int t = w * 16 + tb;   // 16B-aligned (t % 4 == 0)
            ulonglong2 er2[4], vc2[2];
            #pragma unroll
            for (int jr = 0; jr < 4; jr++)
                er2[jr] = *(const ulonglong2*)&e_sm[cur][rg * 4 + jr][t];
            #pragma unroll
            for (int jc = 0; jc < 2; jc++)
                vc2[jc] = *(const ulonglong2*)&v_sm[cur][cg * 2 + jc][t];
            #pragma unroll
            for (int jr = 0; jr < 4; jr++) {
                #pragma unroll
                for (int jc = 0; jc < 2; jc++) {
                    accp[jr][jc] = fma2(er2[jr].x, vc2[jc].x, accp[jr][jc]);
                    accp[jr][jc] = fma2(er2[jr].y, vc2[jc].y, accp[jr][jc]);
                }
            }
        }

        // ---- stage tile+1 into buffer `nxt` (safe: last read fenced at t-1) ----
        if (tile + 1 < NTILES) {
            float4 e0, e1;
            e0.x = __expf(kv0.x); e0.y = __expf(kv0.y); e0.z = __expf(kv0.z); e0.w = __expf(kv0.w);
            e1.x = __expf(kv1.x); e1.y = __expf(kv1.y); e1.z = __expf(kv1.z); e1.w = __expf(kv1.w);
            rowsum += e0.x + e0.y + e0.z + e0.w + e1.x + e1.y + e1.z + e1.w;
            *(float4*)&e_sm[nxt][pr][4 * t4a] = e0;
            *(float4*)&e_sm[nxt][pr][4 * t4b] = e1;
            *(float4*)&v_sm[nxt][pr][4 * t4a] = vv0;
            *(float4*)&v_sm[nxt][pr][4 * t4b] = vv1;
        }
        __syncthreads();
    }

    // ---- block epilogue: horizontal add, reduce 8 warp-tiles, write partials ----
    #pragma unroll
    for (int jr = 0; jr < 4; jr++)
        #pragma unroll
        for (int jc = 0; jc < 2; jc++) {
            float lo, hi;
            unpack2(accp[jr][jc], lo, hi);
            red_sm[w * 256 + (rg * 4 + jr) * 16 + (cg * 2 + jc)] = lo + hi;
        }
    rs_sm[tid] = rowsum;
    __syncthreads();

    float p = 0.f;
    #pragma unroll
    for (int ww = 0; ww < 8; ww++) p += red_sm[ww * 256 + tid];
    g_pctx[bh][chunk][tid >> 4][tid & 15] = p;

    if (tid < HC) {
        float s = 0.f;
        #pragma unroll
        for (int j = 0; j < 16; j++) s += rs_sm[tid * 16 + j];
        g_psum[bh][chunk][tid] = s;
    }
}

// ---------------------------------------------------------------------------
// Kernel 1.5: reduce chunk partials, normalize by row sums -> g_ctx
// ---------------------------------------------------------------------------
__global__ __launch_bounds__(256)
void ctx_reduce_kernel() {
    __shared__ float sinv[HC];
    const int bh  = blockIdx.x;
    const int tid = threadIdx.x;

    if (tid < HC) {
        float s = 0.f;
        #pragma unroll
        for (int c = 0; c < CHUNKS; c++) s += g_psum[bh][c][tid];
        sinv[tid] = 1.0f / s;
    }
    __syncthreads();

    const int r = tid >> 4, cc = tid & 15;
    float a = 0.f;
    #pragma unroll
    for (int c = 0; c < CHUNKS; c++) a += g_pctx[bh][c][r][cc];
    g_ctx[bh][r][cc] = a * sinv[r];
}

// ---------------------------------------------------------------------------
// Kernel 2: out[v][n] = (sum_k ctx[k][v] * exp(k[k,n])) / (sum_k exp(k[k,n]))
// R4 version (measured in the 72.4 us total): 4 adjacent columns per thread,
// ctx pre-duplicated in smem as float2{c,c} so the inner loop is pure FFMA2.
// ---------------------------------------------------------------------------
__global__ __launch_bounds__(256)
void attend_kernel(const float* __restrict__ x2, float* __restrict__ out) {
    __shared__ float2 cdup[HC][HC];   // cdup[k][v] = {ctx[k][v], ctx[k][v]}

    const int tid = threadIdx.x;
    const int h   = blockIdx.y;
    const int b   = blockIdx.z;
    const int bh  = b * HEADS + h;

    {
        const int k = tid >> 4, v = tid & 15;
        const float c = g_ctx[bh][k][v];
        cdup[k][v] = make_float2(c, c);
    }

    const int nn = blockIdx.x * COLS2 + 4 * tid;
    const float* kbase = x2  + (b * Cq + h * HC) * Nq + nn;
    float*       obase = out + (b * Cq + h * HC) * Nq + nn;
    __syncthreads();

    unsigned long long acc01[HC], acc23[HC];
    #pragma unroll
    for (int v = 0; v < HC; v++) { acc01[v] = 0ull; acc23[v] = 0ull; }
    unsigned long long s01 = 0ull, s23 = 0ull;

    #pragma unroll
    for (int k = 0; k < HC; k++) {
        float4 kv = *(const float4*)(kbase + k * Nq);
        const unsigned long long e01 = pack2(__expf(kv.x), __expf(kv.y));
        const unsigned long long e23 = pack2(__expf(kv.z), __expf(kv.w));
        s01 = add2(s01, e01);
        s23 = add2(s23, e23);
        #pragma unroll
        for (int v = 0; v < HC; v += 2) {
            ulonglong2 c2 = *(const ulonglong2*)&cdup[k][v];
            acc01[v]     = fma2(e01, c2.x, acc01[v]);
            acc23[v]     = fma2(e23, c2.x, acc23[v]);
            acc01[v + 1] = fma2(e01, c2.y, acc01[v + 1]);
            acc23[v + 1] = fma2(e23, c2.y, acc23[v + 1]);
        }
    }

    float sx, sy, sz, sw;
    unpack2(s01, sx, sy);
    unpack2(s23, sz, sw);
    const float rx = 1.0f / sx, ry = 1.0f / sy;
    const float rz = 1.0f / sz, rw = 1.0f / sw;

    #pragma unroll
    for (int v = 0; v < HC; v++) {
        float ax, ay, az, aw;
        unpack2(acc01[v], ax, ay);
        unpack2(acc23[v], az, aw);
        float4 o;
        o.x = ax * rx;
        o.y = ay * ry;
        o.z = az * rz;
        o.w = aw * rw;
        *(float4*)(obase + v * Nq) = o;
    }
}

// ---------------------------------------------------------------------------
extern "C" void kernel_launch(void* const* d_in, const int* in_sizes, int n_in,
                              void* d_out, int out_size) {
    const float* x1 = (const float*)d_in[0];   // values
    const float* x2 = (const float*)d_in[1];   // keys / queries
    float* out = (float*)d_out;

    ctx_partial_kernel<<<dim3(CHUNKS, HEADS, Bq), 256>>>(x1, x2);
    ctx_reduce_kernel<<<NBH, 256>>>();
    attend_kernel<<<dim3(Nq / COLS2, HEADS, Bq), 256>>>(x2, out);
}

// round 12
// speedup vs baseline: 1.2559x; 1.0046x over previous
#include <cuda_runtime.h>

// Problem constants
#define Bq     8
#define Cq     128
#define HEADS  8
#define HC     16            // channels per head
#define Nq     16384         // H*W
#define NBH    (Bq*HEADS)    // 64

// Kernel-1 tiling (measured best: R11)
#define CHUNKS      16
#define CHUNK_COLS  (Nq/CHUNKS)        // 1024
#define TILE        128
#define NTILES      (CHUNK_COLS/TILE)  // 8
#define PAD         132                // row stride (528B = 33*16 -> 16B-aligned)

// Kernel-2 tiling: 2 columns per thread, 256 threads -> 512 columns per block
#define COLS2       512

// Scratch (no allocations allowed -> __device__ globals)
__device__ float g_pctx[NBH][CHUNKS][HC][HC];   // unnormalized partial context
__device__ float g_psum[NBH][CHUNKS][HC];       // partial row sums of exp(k)

// ---- packed f32x2 helpers (ptxas never auto-fuses) ----
__device__ __forceinline__ unsigned long long fma2(unsigned long long a,
                                                   unsigned long long b,
                                                   unsigned long long c) {
    unsigned long long d;
    asm("fma.rn.f32x2 %0, %1, %2, %3;" : "=l"(d) : "l"(a), "l"(b), "l"(c));
    return d;
}
__device__ __forceinline__ unsigned long long pack2(float lo, float hi) {
    unsigned long long d;
    asm("mov.b64 %0, {%1, %2};" : "=l"(d) : "f"(lo), "f"(hi));
    return d;
}
__device__ __forceinline__ void unpack2(unsigned long long v, float& lo, float& hi) {
    asm("mov.b64 {%0, %1}, %2;" : "=f"(lo), "=f"(hi) : "l"(v));
}

// ---------------------------------------------------------------------------
// Kernel 1 (FROZEN at R11-measured form): per (b,h,chunk) partial
//   ctx'[r][c] = sum_n exp(k[r,n]) * v[c,n],  rowsum[r] = sum_n exp(k[r,n])
// 256 threads, double-buffered smem pipeline, one barrier per tile,
// f32x2-packed accumulation. Grid 1024 -> 4 CTAs/SM wave 1.
// ---------------------------------------------------------------------------
__global__ __launch_bounds__(256)
void ctx_partial_kernel(const float* __restrict__ x1, const float* __restrict__ x2) {
    __shared__ float e_sm[2][HC][PAD];
    __shared__ float v_sm[2][HC][PAD];
    __shared__ float red_sm[8 * 256];   // per-warp ctx partials
    __shared__ float rs_sm[256];        // per-thread row sums

    const int tid   = threadIdx.x;
    const int chunk = blockIdx.x;
    const int h     = blockIdx.y;
    const int b     = blockIdx.z;
    const int bh    = b * HEADS + h;

    const int base  = (b * Cq + h * HC) * Nq + chunk * CHUNK_COLS;
    const float* kptr = x2 + base;   // keys/queries come from x2
    const float* vptr = x1 + base;   // values come from x1

    const int pr = tid >> 4;   // producer row (0..15)
    const int pl = tid & 15;   // producer lane within row
    const int w  = tid >> 5;   // warp id (0..7)
    const int l  = tid & 31;
    const int rg = l >> 3;     // row group: rows rg*4 .. rg*4+3
    const int cg = l & 7;      // col group: cols cg*2, cg*2+1

    unsigned long long accp[4][2];   // packed partial-pair accumulators
    #pragma unroll
    for (int a = 0; a < 4; a++) { accp[a][0] = 0ull; accp[a][1] = 0ull; }
    float rowsum = 0.f;

    const int t4a = pl;            // float4 index 0..15
    const int t4b = pl + 16;       // float4 index 16..31

    float4 kv0, kv1, vv0, vv1;     // staging registers for the in-flight tile

    // ---- prologue: load + stage tile 0 into buffer 0 ----
    {
        const int off = pr * Nq;
        kv0 = *(const float4*)(kptr + off + 4 * t4a);
        kv1 = *(const float4*)(kptr + off + 4 * t4b);
        vv0 = *(const float4*)(vptr + off + 4 * t4a);
        vv1 = *(const float4*)(vptr + off + 4 * t4b);
        float4 e0, e1;
        e0.x = __expf(kv0.x); e0.y = __expf(kv0.y); e0.z = __expf(kv0.z); e0.w = __expf(kv0.w);
        e1.x = __expf(kv1.x); e1.y = __expf(kv1.y); e1.z = __expf(kv1.z); e1.w = __expf(kv1.w);
        rowsum += e0.x + e0.y + e0.z + e0.w + e1.x + e1.y + e1.z + e1.w;
        *(float4*)&e_sm[0][pr][4 * t4a] = e0;
        *(float4*)&e_sm[0][pr][4 * t4b] = e1;
        *(float4*)&v_sm[0][pr][4 * t4a] = vv0;
        *(float4*)&v_sm[0][pr][4 * t4b] = vv1;
    }
    __syncthreads();

    for (int tile = 0; tile < NTILES; tile++) {
        const int cur = tile & 1;
        const int nxt = cur ^ 1;

        // ---- issue loads for tile+1 (latency hidden by consume below) ----
        if (tile + 1 < NTILES) {
            const int off = pr * Nq + (tile + 1) * TILE;
            kv0 = *(const float4*)(kptr + off + 4 * t4a);
            kv1 = *(const float4*)(kptr + off + 4 * t4b);
            vv0 = *(const float4*)(vptr + off + 4 * t4a);
            vv1 = *(const float4*)(vptr + off + 4 * t4b);
        }

        // ---- consume tile from smem buffer `cur` (f32x2-packed FMAs) ----
        #pragma unroll
        for (int tb = 0; tb < 16; tb += 4) {
            const int t = w * 16 + tb;   // 16B-aligned (t % 4 == 0)
            ulonglong2 er2[4], vc2[2];
            #pragma unroll
            for (int jr = 0; jr < 4; jr++)
                er2[jr] = *(const ulonglong2*)&e_sm[cur][rg * 4 + jr][t];
            #pragma unroll
            for (int jc = 0; jc < 2; jc++)
                vc2[jc] = *(const ulonglong2*)&v_sm[cur][cg * 2 + jc][t];
            #pragma unroll
            for (int jr = 0; jr < 4; jr++) {
                #pragma unroll
                for (int jc = 0; jc < 2; jc++) {
                    accp[jr][jc] = fma2(er2[jr].x, vc2[jc].x, accp[jr][jc]);
                    accp[jr][jc] = fma2(er2[jr].y, vc2[jc].y, accp[jr][jc]);
                }
            }
        }

        // ---- stage tile+1 into buffer `nxt` (safe: last read fenced at t-1) ----
        if (tile + 1 < NTILES) {
            float4 e0, e1;
            e0.x = __expf(kv0.x); e0.y = __expf(kv0.y); e0.z = __expf(kv0.z); e0.w = __expf(kv0.w);
            e1.x = __expf(kv1.x); e1.y = __expf(kv1.y); e1.z = __expf(kv1.z); e1.w = __expf(kv1.w);
            rowsum += e0.x + e0.y + e0.z + e0.w + e1.x + e1.y + e1.z + e1.w;
            *(float4*)&e_sm[nxt][pr][4 * t4a] = e0;
            *(float4*)&e_sm[nxt][pr][4 * t4b] = e1;
            *(float4*)&v_sm[nxt][pr][4 * t4a] = vv0;
            *(float4*)&v_sm[nxt][pr][4 * t4b] = vv1;
        }
        __syncthreads();
    }

    // ---- block epilogue: horizontal add, reduce 8 warp-tiles, write partials ----
    #pragma unroll
    for (int jr = 0; jr < 4; jr++)
        #pragma unroll
        for (int jc = 0; jc < 2; jc++) {
            float lo, hi;
            unpack2(accp[jr][jc], lo, hi);
            red_sm[w * 256 + (rg * 4 + jr) * 16 + (cg * 2 + jc)] = lo + hi;
        }
    rs_sm[tid] = rowsum;
    __syncthreads();

    float p = 0.f;
    #pragma unroll
    for (int ww = 0; ww < 8; ww++) p += red_sm[ww * 256 + tid];
    g_pctx[bh][chunk][tid >> 4][tid & 15] = p;

    if (tid < HC) {
        float s = 0.f;
        #pragma unroll
        for (int j = 0; j < 16; j++) s += rs_sm[tid * 16 + j];
        g_psum[bh][chunk][tid] = s;
    }
}

// ---------------------------------------------------------------------------
// Kernel 2 (fused reduce + attend):
//   ctx[k][v]  = (sum_chunk pctx) / (sum_chunk psum[k])   [inline, L2-hot]
//   out[v][n]  = (sum_k ctx[k][v] * exp(k[k,n])) / (sum_k exp(k[k,n]))
// 2 columns per thread, accumulators packed over the v-dimension so ctx pairs
// load straight from smem (broadcast LDS, no dup); only exp is duplicated.
// ~52 regs -> 4 CTAs/SM resident.
// ---------------------------------------------------------------------------
__global__ __launch_bounds__(256, 4)
void attend_kernel(const float* __restrict__ x2, float* __restrict__ out) {
    __shared__ float ctx_sm[HC][HC];   // normalized ctx[k][v], rows 64B
    __shared__ float sinv_sm[HC];

    const int tid = threadIdx.x;
    const int h   = blockIdx.y;
    const int b   = blockIdx.z;
    const int bh  = b * HEADS + h;

    // ---- inline reduce of K1 partials (all reads L2-hot) ----
    if (tid < HC) {
        float s = 0.f;
        #pragma unroll
        for (int c = 0; c < CHUNKS; c++) s += g_psum[bh][c][tid];
        sinv_sm[tid] = 1.0f / s;
    }
    float a = 0.f;
    #pragma unroll
    for (int c = 0; c < CHUNKS; c++)
        a += ((const float*)g_pctx[bh][c])[tid];       // coalesced per chunk
    __syncthreads();
    ctx_sm[tid >> 4][tid & 15] = a * sinv_sm[tid >> 4];

    const int nn = blockIdx.x * COLS2 + 2 * tid;
    const float* kbase = x2  + (b * Cq + h * HC) * Nq + nn;
    float*       obase = out + (b * Cq + h * HC) * Nq + nn;
    __syncthreads();

    // accA: column n, accB: column n+1; each holds 8 packed {v, v+1} pairs
    unsigned long long accA[8], accB[8];
    #pragma unroll
    for (int j = 0; j < 8; j++) { accA[j] = 0ull; accB[j] = 0ull; }
    float sx = 0.f, sy = 0.f;

    #pragma unroll
    for (int k = 0; k < HC; k++) {
        float2 kv = *(const float2*)(kbase + k * Nq);
        const float ex = __expf(kv.x), ey = __expf(kv.y);
        sx += ex; sy += ey;
        const unsigned long long eA = pack2(ex, ex);
        const unsigned long long eB = pack2(ey, ey);
        #pragma unroll
        for (int v = 0; v < HC; v += 4) {
            // {ctx[k][v],ctx[k][v+1]},{ctx[k][v+2],ctx[k][v+3]} in one LDS.128
            ulonglong2 c2 = *(const ulonglong2*)&ctx_sm[k][v];
            accA[v / 2]     = fma2(eA, c2.x, accA[v / 2]);
            accB[v / 2]     = fma2(eB, c2.x, accB[v / 2]);
            accA[v / 2 + 1] = fma2(eA, c2.y, accA[v / 2 + 1]);
            accB[v / 2 + 1] = fma2(eB, c2.y, accB[v / 2 + 1]);
        }
    }

    const float rx = 1.0f / sx, ry = 1.0f / sy;
    #pragma unroll
    for (int j = 0; j < 8; j++) {
        float a0, a1, b0, b1;
        unpack2(accA[j], a0, a1);   // rows 2j, 2j+1 for column n
        unpack2(accB[j], b0, b1);   // rows 2j, 2j+1 for column n+1
        float2 o0, o1;
        o0.x = a0 * rx; o0.y = b0 * ry;
        o1.x = a1 * rx; o1.y = b1 * ry;
        *(float2*)(obase + (2 * j)     * Nq) = o0;
        *(float2*)(obase + (2 * j + 1) * Nq) = o1;
    }
}

// ---------------------------------------------------------------------------
extern "C" void kernel_launch(void* const* d_in, const int* in_sizes, int n_in,
                              void* d_out, int out_size) {
    const float* x1 = (const float*)d_in[0];   // values
    const float* x2 = (const float*)d_in[1];   // keys / queries
    float* out = (float*)d_out;

    ctx_partial_kernel<<<dim3(CHUNKS, HEADS, Bq), 256>>>(x1, x2);
    attend_kernel<<<dim3(Nq / COLS2, HEADS, Bq), 256>>>(x2, out);
}